// round 2
// baseline (speedup 1.0000x reference)
#include <cuda_runtime.h>
#include <math.h>

#define BATCH  256
#define SEQ    64
#define DMODEL 512
#define HDIM   512
#define NHEAD  8
#define DK     64
#define EPS_F  1e-7f

#define OUT_ELEMS  (BATCH * SEQ * DMODEL)          // 8388608
#define ATTN_ELEMS (NHEAD * BATCH * SEQ * SEQ)     // 8388608
#define ATTN_OFF   OUT_ELEMS
#define SCALAR_OFF (OUT_ELEMS + ATTN_ELEMS)

// Scratch (device globals; allocation-free per harness rules)
__device__ float g_qh[BATCH * SEQ * HDIM];
__device__ float g_kh[BATCH * SEQ * HDIM];
__device__ float g_vh[BATCH * SEQ * HDIM];
__device__ float g_o [BATCH * SEQ * HDIM];

// ---------------------------------------------------------------------------
// Kernel A: group-linear projections.
//   For proj p in {q,k,v}, position n: Y[b, n, o] = sum_d X[b, n, d] * W[n, d, o]
//   Per (p, n): GEMM (256 x 512) x (512 x 512). Tile 64x64, BK=16, 4x4/thread.
// grid = (4, 8, 192)  [Mtile, Otile, p*64+n], block = 256
// ---------------------------------------------------------------------------
__global__ __launch_bounds__(256) void proj_kernel(
    const float* __restrict__ q, const float* __restrict__ k, const float* __restrict__ v,
    const float* __restrict__ Wq, const float* __restrict__ Wk, const float* __restrict__ Wv)
{
    __shared__ float As[64][16];   // [m][kk]
    __shared__ float Bs[16][64];   // [kk][o]

    const int z    = blockIdx.z;
    const int proj = z >> 6;
    const int n    = z & 63;

    const float* X;
    const float* W;
    float* Y;
    if (proj == 0)      { X = q; W = Wq; Y = g_qh; }
    else if (proj == 1) { X = k; W = Wk; Y = g_kh; }
    else                { X = v; W = Wv; Y = g_vh; }

    const int m0 = blockIdx.x * 64;   // batch tile
    const int o0 = blockIdx.y * 64;   // output-feature tile

    const int tid = threadIdx.x;
    const int tx  = tid & 15;         // o quadrant
    const int ty  = tid >> 4;         // m quadrant

    // loaders
    const int am = tid >> 2;          // A row   (0..63)
    const int av = (tid & 3) * 4;     // A k-col (0,4,8,12)
    const int bk = tid >> 4;          // B row   (0..15)
    const int bo = (tid & 15) * 4;    // B o-col (0..60)

    const float* Aptr = X + (size_t)m0 * SEQ * DMODEL + (size_t)n * DMODEL;
    const float* Bptr = W + (size_t)n * DMODEL * HDIM + o0;

    float acc[4][4] = {};

    for (int k0 = 0; k0 < DMODEL; k0 += 16) {
        float4 a4 = *reinterpret_cast<const float4*>(Aptr + (size_t)am * (SEQ * DMODEL) + k0 + av);
        float4 b4 = *reinterpret_cast<const float4*>(Bptr + (size_t)(k0 + bk) * HDIM + bo);
        *reinterpret_cast<float4*>(&As[am][av]) = a4;
        *reinterpret_cast<float4*>(&Bs[bk][bo]) = b4;
        __syncthreads();

        #pragma unroll
        for (int kk = 0; kk < 16; kk++) {
            float4 bb = *reinterpret_cast<const float4*>(&Bs[kk][tx * 4]);
            #pragma unroll
            for (int ii = 0; ii < 4; ii++) {
                float a = As[ty * 4 + ii][kk];
                acc[ii][0] += a * bb.x;
                acc[ii][1] += a * bb.y;
                acc[ii][2] += a * bb.z;
                acc[ii][3] += a * bb.w;
            }
        }
        __syncthreads();
    }

    #pragma unroll
    for (int ii = 0; ii < 4; ii++) {
        int b = m0 + ty * 4 + ii;
        float4 r = make_float4(acc[ii][0], acc[ii][1], acc[ii][2], acc[ii][3]);
        *reinterpret_cast<float4*>(Y + ((size_t)b * SEQ + n) * HDIM + o0 + tx * 4) = r;
    }
}

// ---------------------------------------------------------------------------
// Kernel B: attention per (b, h).
//   S = qh . kh^T / 8 ; softmax ; top-5 sparsify+renorm ; O = P . vh
//   Writes sparsified attn into d_out[ATTN_OFF + ((h*B + b)*64 + q)*64 + k].
// grid = 2048 (b*8 + h), block = 256.  Static smem = 48 KB (V reuses Q buffer).
// ---------------------------------------------------------------------------
__global__ __launch_bounds__(256) void attn_kernel(float* __restrict__ d_out, int write_attn)
{
    __shared__ float qs[SEQ * 64];   // Q tile [qq][d]; later reused for V [j][d]
    __shared__ float ks[SEQ * 64];   // K tile transposed: ks[d*64 + j]
    __shared__ float sc[SEQ * 64];   // scores / probs [qq][j]

    const int bh = blockIdx.x;
    const int b  = bh >> 3;
    const int h  = bh & 7;

    const int tid  = threadIdx.x;
    const int lane = tid & 31;
    const int warp = tid >> 5;
    const int tx   = tid & 15;
    const int ty   = tid >> 4;

    const float* qb = g_qh + (size_t)b * SEQ * HDIM + (size_t)h * DK;
    const float* kb = g_kh + (size_t)b * SEQ * HDIM + (size_t)h * DK;
    const float* vb = g_vh + (size_t)b * SEQ * HDIM + (size_t)h * DK;

    // Phase 1: load Q (natural) and K (transposed).
    for (int i = tid; i < 1024; i += 256) {
        int r = i >> 4, c = (i & 15) * 4;
        *reinterpret_cast<float4*>(&qs[r * 64 + c]) =
            *reinterpret_cast<const float4*>(qb + (size_t)r * HDIM + c);
    }
    for (int i = tid; i < 1024; i += 256) {
        int r = i & 63, c = (i >> 6) * 4;
        float4 kv = *reinterpret_cast<const float4*>(kb + (size_t)r * HDIM + c);
        ks[(c + 0) * 64 + r] = kv.x;
        ks[(c + 1) * 64 + r] = kv.y;
        ks[(c + 2) * 64 + r] = kv.z;
        ks[(c + 3) * 64 + r] = kv.w;
    }
    __syncthreads();

    // Phase 2: S = Q K^T / sqrt(64)
    {
        float acc[4][4] = {};
        #pragma unroll 4
        for (int d = 0; d < 64; d++) {
            float4 bb = *reinterpret_cast<const float4*>(&ks[d * 64 + tx * 4]);
            #pragma unroll
            for (int ii = 0; ii < 4; ii++) {
                float a = qs[(ty * 4 + ii) * 64 + d];
                acc[ii][0] += a * bb.x;
                acc[ii][1] += a * bb.y;
                acc[ii][2] += a * bb.z;
                acc[ii][3] += a * bb.w;
            }
        }
        #pragma unroll
        for (int ii = 0; ii < 4; ii++)
            #pragma unroll
            for (int jj = 0; jj < 4; jj++)
                sc[(ty * 4 + ii) * 64 + tx * 4 + jj] = acc[ii][jj] * 0.125f;
    }
    __syncthreads();

    // Phase 3: load V into qs buffer; softmax + top-5 renorm per row (warp-per-8-rows).
    for (int i = tid; i < 1024; i += 256) {
        int r = i >> 4, c = (i & 15) * 4;
        *reinterpret_cast<float4*>(&qs[r * 64 + c]) =
            *reinterpret_cast<const float4*>(vb + (size_t)r * HDIM + c);
    }

    const unsigned FULL = 0xffffffffu;
    for (int rr = 0; rr < 8; rr++) {
        int r = warp * 8 + rr;
        float s0 = sc[r * 64 + lane];
        float s1 = sc[r * 64 + 32 + lane];

        float m = fmaxf(s0, s1);
        #pragma unroll
        for (int off = 16; off; off >>= 1) m = fmaxf(m, __shfl_xor_sync(FULL, m, off));
        float e0 = expf(s0 - m), e1 = expf(s1 - m);
        float s = e0 + e1;
        #pragma unroll
        for (int off = 16; off; off >>= 1) s += __shfl_xor_sync(FULL, s, off);
        float p0 = e0 / s, p1 = e1 / s;

        // 5th-largest via 5x (max-reduce + remove one instance)
        float a = p0, c = p1, kth = 0.0f;
        #pragma unroll
        for (int t = 0; t < 5; t++) {
            float mm = fmaxf(a, c);
            #pragma unroll
            for (int off = 16; off; off >>= 1) mm = fmaxf(mm, __shfl_xor_sync(FULL, mm, off));
            kth = mm;
            unsigned ba = __ballot_sync(FULL, a == mm);
            unsigned bc = __ballot_sync(FULL, c == mm);
            if (ba) { if (lane == __ffs(ba) - 1) a = -1e30f; }
            else    { if (lane == __ffs(bc) - 1) c = -1e30f; }
        }

        float delta = kth + EPS_F;
        float w0 = fmaxf(p0 - delta, 0.0f);
        float w1 = fmaxf(p1 - delta, 0.0f);
        float ws = w0 + w1;
        #pragma unroll
        for (int off = 16; off; off >>= 1) ws += __shfl_xor_sync(FULL, ws, off);
        float denom = ws + EPS_F;
        w0 /= denom;
        w1 /= denom;

        sc[r * 64 + lane]      = w0;
        sc[r * 64 + 32 + lane] = w1;
        if (write_attn) {
            size_t ab = (size_t)ATTN_OFF + (((size_t)(h * BATCH + b) * 64 + r) * 64);
            d_out[ab + lane]      = w0;
            d_out[ab + 32 + lane] = w1;
        }
    }
    __syncthreads();

    // Phase 4: O = P . V  (V now lives in qs)
    {
        float acc[4][4] = {};
        #pragma unroll 4
        for (int j = 0; j < 64; j++) {
            float4 bb = *reinterpret_cast<const float4*>(&qs[j * 64 + tx * 4]);
            #pragma unroll
            for (int ii = 0; ii < 4; ii++) {
                float p = sc[(ty * 4 + ii) * 64 + j];
                acc[ii][0] += p * bb.x;
                acc[ii][1] += p * bb.y;
                acc[ii][2] += p * bb.z;
                acc[ii][3] += p * bb.w;
            }
        }
        #pragma unroll
        for (int ii = 0; ii < 4; ii++) {
            int qq = ty * 4 + ii;
            float4 r = make_float4(acc[ii][0], acc[ii][1], acc[ii][2], acc[ii][3]);
            *reinterpret_cast<float4*>(g_o + ((size_t)b * SEQ + qq) * HDIM + (size_t)h * DK + tx * 4) = r;
        }
    }
}

// ---------------------------------------------------------------------------
// Kernel C: fused fc + gate GEMMs + gated-tanh epilogue.
//   rows m over B*N (16384), cols o over D (512):
//   out[m,o] = sigmoid(x.gate_w^T + gb) * tanh(x.fc_w^T + fb)
// grid = (256, 8), block = 256
// ---------------------------------------------------------------------------
__global__ __launch_bounds__(256) void out_kernel(
    const float* __restrict__ fc_w, const float* __restrict__ fc_b,
    const float* __restrict__ gw,   const float* __restrict__ gb,
    float* __restrict__ d_out, int write_scalar)
{
    __shared__ float As[64][16];   // [m][kk]
    __shared__ float Bf[16][68];   // [kk][o], padded rows (float4-aligned: 272B)
    __shared__ float Bg[16][68];

    const int m0 = blockIdx.x * 64;
    const int o0 = blockIdx.y * 64;

    const int tid = threadIdx.x;
    const int tx  = tid & 15;
    const int ty  = tid >> 4;

    const int am = tid >> 2;
    const int av = (tid & 3) * 4;
    const int bo = tid >> 2;          // weight row (o), 0..63
    const int bv = (tid & 3) * 4;     // weight k-col, {0,4,8,12}

    float af[4][4] = {};
    float ag[4][4] = {};

    for (int k0 = 0; k0 < HDIM; k0 += 16) {
        *reinterpret_cast<float4*>(&As[am][av]) =
            *reinterpret_cast<const float4*>(g_o + (size_t)(m0 + am) * HDIM + k0 + av);
        float4 f4 = *reinterpret_cast<const float4*>(fc_w + (size_t)(o0 + bo) * HDIM + k0 + bv);
        float4 g4 = *reinterpret_cast<const float4*>(gw   + (size_t)(o0 + bo) * HDIM + k0 + bv);
        Bf[bv + 0][bo] = f4.x; Bf[bv + 1][bo] = f4.y; Bf[bv + 2][bo] = f4.z; Bf[bv + 3][bo] = f4.w;
        Bg[bv + 0][bo] = g4.x; Bg[bv + 1][bo] = g4.y; Bg[bv + 2][bo] = g4.z; Bg[bv + 3][bo] = g4.w;
        __syncthreads();

        #pragma unroll
        for (int kk = 0; kk < 16; kk++) {
            float4 bf = *reinterpret_cast<const float4*>(&Bf[kk][tx * 4]);
            float4 bgv = *reinterpret_cast<const float4*>(&Bg[kk][tx * 4]);
            #pragma unroll
            for (int ii = 0; ii < 4; ii++) {
                float a = As[ty * 4 + ii][kk];
                af[ii][0] += a * bf.x;  af[ii][1] += a * bf.y;
                af[ii][2] += a * bf.z;  af[ii][3] += a * bf.w;
                ag[ii][0] += a * bgv.x; ag[ii][1] += a * bgv.y;
                ag[ii][2] += a * bgv.z; ag[ii][3] += a * bgv.w;
            }
        }
        __syncthreads();
    }

    #pragma unroll
    for (int ii = 0; ii < 4; ii++) {
        int m = m0 + ty * 4 + ii;
        float vals[4];
        #pragma unroll
        for (int jj = 0; jj < 4; jj++) {
            int o = o0 + tx * 4 + jj;
            float fcv = af[ii][jj] + fc_b[o];
            float gv  = ag[ii][jj] + gb[o];
            float sig = 1.0f / (1.0f + expf(-gv));
            vals[jj] = sig * tanhf(fcv);
        }
        float4 r = make_float4(vals[0], vals[1], vals[2], vals[3]);
        *reinterpret_cast<float4*>(d_out + (size_t)m * DMODEL + o0 + tx * 4) = r;
    }

    if (write_scalar && blockIdx.x == 0 && blockIdx.y == 0 && tid == 0)
        d_out[SCALAR_OFF] = 0.0f;
}

// ---------------------------------------------------------------------------
extern "C" void kernel_launch(void* const* d_in, const int* in_sizes, int n_in,
                              void* d_out, int out_size)
{
    const float* q      = (const float*)d_in[0];
    const float* k      = (const float*)d_in[1];
    const float* v      = (const float*)d_in[2];
    const float* Wq     = (const float*)d_in[3];
    const float* Wk     = (const float*)d_in[4];
    const float* Wv     = (const float*)d_in[5];
    const float* fc_w   = (const float*)d_in[6];
    const float* fc_b   = (const float*)d_in[7];
    const float* gate_w = (const float*)d_in[8];
    const float* gate_b = (const float*)d_in[9];
    float* out = (float*)d_out;

    const int write_attn   = (out_size >= ATTN_OFF + ATTN_ELEMS) ? 1 : 0;
    const int write_scalar = (out_size >= SCALAR_OFF + 1) ? 1 : 0;

    dim3 gA(4, 8, 192);
    proj_kernel<<<gA, 256>>>(q, k, v, Wq, Wk, Wv);

    attn_kernel<<<2048, 256>>>(out, write_attn);

    dim3 gC(256, 8);
    out_kernel<<<gC, 256>>>(fc_w, fc_b, gate_w, gate_b, out, write_scalar);
}

// round 5
// speedup vs baseline: 1.8148x; 1.8148x over previous
#include <cuda_runtime.h>
#include <cuda_bf16.h>
#include <cstdint>
#include <math.h>

#define BATCH  256
#define SEQ    64
#define DMODEL 512
#define HDIM   512
#define NHEAD  8
#define DK     64
#define EPS_F  1e-7f

#define OUT_ELEMS  (BATCH * SEQ * DMODEL)          // 8388608
#define ATTN_ELEMS (NHEAD * BATCH * SEQ * SEQ)     // 8388608
#define ATTN_OFF   OUT_ELEMS
#define SCALAR_OFF (OUT_ELEMS + ATTN_ELEMS)

// Scratch (device globals; allocation-free per harness rules)
__device__ float g_qh[BATCH * SEQ * HDIM];
__device__ float g_kh[BATCH * SEQ * HDIM];
__device__ float g_vh[BATCH * SEQ * HDIM];
__device__ float g_o [BATCH * SEQ * HDIM];

// ---------------------------------------------------------------------------
// bf16 split helpers: x = hi + lo, both bf16. Packed pairs (k, k+1) in b32.
// ---------------------------------------------------------------------------
__device__ __forceinline__ void bsplit2(float x, float y, uint32_t& h, uint32_t& l) {
    __nv_bfloat16 hx = __float2bfloat16_rn(x);
    __nv_bfloat16 hy = __float2bfloat16_rn(y);
    float rx = x - __bfloat162float(hx);
    float ry = y - __bfloat162float(hy);
    __nv_bfloat16 lx = __float2bfloat16_rn(rx);
    __nv_bfloat16 ly = __float2bfloat16_rn(ry);
    h = (uint32_t)__bfloat16_as_ushort(hx) | ((uint32_t)__bfloat16_as_ushort(hy) << 16);
    l = (uint32_t)__bfloat16_as_ushort(lx) | ((uint32_t)__bfloat16_as_ushort(ly) << 16);
}

// D += A(16x16) * B(16x8), bf16 inputs, fp32 accum (legacy path, plain sm_103)
__device__ __forceinline__ void mma_bf16(float* c, const uint32_t* a, const uint32_t* b) {
    asm volatile(
        "mma.sync.aligned.m16n8k16.row.col.f32.bf16.bf16.f32 "
        "{%0,%1,%2,%3}, {%4,%5,%6,%7}, {%8,%9}, {%0,%1,%2,%3};"
        : "+f"(c[0]), "+f"(c[1]), "+f"(c[2]), "+f"(c[3])
        : "r"(a[0]), "r"(a[1]), "r"(a[2]), "r"(a[3]), "r"(b[0]), "r"(b[1]));
}

#define PA   12    // A/[o][kp] pitch in uint32 (8 kpairs + 4 pad): frag bank 12g+t distinct
#define PBP  136   // proj B [kp][o] pitch: frag bank 8t+g distinct

// ---------------------------------------------------------------------------
// Kernel A: group-linear projections via split-bf16 mma.sync.
//   Per (proj, n): (256 x 512) @ (512 x 512). CTA tile M=128, N=128, BK=16.
//   8 warps as 2x4 (m x n); warp tile 64x32; m16n8k16 frags; 3-MMA split.
// grid = (2, 4, 192), block = 256
// ---------------------------------------------------------------------------
__global__ __launch_bounds__(256, 2) void proj_mma(
    const float* __restrict__ q, const float* __restrict__ kin, const float* __restrict__ v,
    const float* __restrict__ Wq, const float* __restrict__ Wk, const float* __restrict__ Wv)
{
    __shared__ __align__(16) uint32_t Ahi[128 * PA], Alo[128 * PA];   // [m][kpair]
    __shared__ __align__(16) uint32_t Bhi[8 * PBP],  Blo[8 * PBP];    // [kpair][o]

    const int z = blockIdx.z;
    const int proj = z >> 6, n = z & 63;
    const float* X; const float* W; float* Y;
    if (proj == 0)      { X = q;   W = Wq; Y = g_qh; }
    else if (proj == 1) { X = kin; W = Wk; Y = g_kh; }
    else                { X = v;   W = Wv; Y = g_vh; }

    const int m0 = blockIdx.x * 128;
    const int o0 = blockIdx.y * 128;

    const int tid  = threadIdx.x;
    const int wid  = tid >> 5;
    const int lane = tid & 31;
    const int g    = lane >> 2;
    const int t    = lane & 3;
    const int warp_m = (wid & 1) * 64;
    const int warp_n = (wid >> 1) * 32;

    const int ar = tid >> 1, sA = (tid & 1);        // A: row, k-half (0/1 -> k 0..7 / 8..15)
    const int kp = tid >> 5, og = (lane) * 4;       // B: kpair row, o-offset

    float acc[4][4][4] = {};

    for (int it = 0; it < 32; ++it) {
        const int k0 = it * 16;

        // A tile: pack 8 consecutive k into 4 (hi,lo) pairs
        {
            const float* ap = X + (size_t)(m0 + ar) * (SEQ * DMODEL) + (size_t)n * DMODEL + k0 + sA * 8;
            float4 f0 = *(const float4*)ap;
            float4 f1 = *(const float4*)(ap + 4);
            uint4 H, L;
            bsplit2(f0.x, f0.y, H.x, L.x);
            bsplit2(f0.z, f0.w, H.y, L.y);
            bsplit2(f1.x, f1.y, H.z, L.z);
            bsplit2(f1.z, f1.w, H.w, L.w);
            *(uint4*)&Ahi[ar * PA + sA * 4] = H;
            *(uint4*)&Alo[ar * PA + sA * 4] = L;
        }
        // B tile: W[k][o] rows k=2kp, 2kp+1 -> packed pairs per o
        {
            const float* bp = W + (size_t)n * (DMODEL * HDIM) + (size_t)(k0 + 2 * kp) * HDIM + o0 + og;
            float4 f0 = *(const float4*)bp;          // k = 2kp,   o..o+3
            float4 f1 = *(const float4*)(bp + HDIM); // k = 2kp+1, o..o+3
            uint4 H, L;
            bsplit2(f0.x, f1.x, H.x, L.x);
            bsplit2(f0.y, f1.y, H.y, L.y);
            bsplit2(f0.z, f1.z, H.z, L.z);
            bsplit2(f0.w, f1.w, H.w, L.w);
            *(uint4*)&Bhi[kp * PBP + og] = H;
            *(uint4*)&Blo[kp * PBP + og] = L;
        }
        __syncthreads();

        uint32_t af[4][4], bh[4][2], bx[4][2];
        #pragma unroll
        for (int mi = 0; mi < 4; ++mi) {
            const int rb = warp_m + mi * 16;
            af[mi][0] = Ahi[(rb + g)     * PA + t];
            af[mi][1] = Ahi[(rb + g + 8) * PA + t];
            af[mi][2] = Ahi[(rb + g)     * PA + t + 4];
            af[mi][3] = Ahi[(rb + g + 8) * PA + t + 4];
        }
        #pragma unroll
        for (int ni = 0; ni < 4; ++ni) {
            const int nb = warp_n + ni * 8;
            bh[ni][0] = Bhi[t       * PBP + nb + g];
            bh[ni][1] = Bhi[(t + 4) * PBP + nb + g];
        }
        #pragma unroll
        for (int mi = 0; mi < 4; ++mi)
            #pragma unroll
            for (int ni = 0; ni < 4; ++ni)
                mma_bf16(acc[mi][ni], af[mi], bh[ni]);    // hi*hi

        #pragma unroll
        for (int ni = 0; ni < 4; ++ni) {
            const int nb = warp_n + ni * 8;
            bx[ni][0] = Blo[t       * PBP + nb + g];
            bx[ni][1] = Blo[(t + 4) * PBP + nb + g];
        }
        #pragma unroll
        for (int mi = 0; mi < 4; ++mi)
            #pragma unroll
            for (int ni = 0; ni < 4; ++ni)
                mma_bf16(acc[mi][ni], af[mi], bx[ni]);    // hi*lo

        #pragma unroll
        for (int mi = 0; mi < 4; ++mi) {
            const int rb = warp_m + mi * 16;
            af[mi][0] = Alo[(rb + g)     * PA + t];
            af[mi][1] = Alo[(rb + g + 8) * PA + t];
            af[mi][2] = Alo[(rb + g)     * PA + t + 4];
            af[mi][3] = Alo[(rb + g + 8) * PA + t + 4];
        }
        #pragma unroll
        for (int mi = 0; mi < 4; ++mi)
            #pragma unroll
            for (int ni = 0; ni < 4; ++ni)
                mma_bf16(acc[mi][ni], af[mi], bh[ni]);    // lo*hi

        __syncthreads();
    }

    // Epilogue: c0 row=g col=2t, c1 col=2t+1, c2/c3 row=g+8
    #pragma unroll
    for (int mi = 0; mi < 4; ++mi) {
        const int r0 = m0 + warp_m + mi * 16 + g;
        #pragma unroll
        for (int ni = 0; ni < 4; ++ni) {
            const int c0 = o0 + warp_n + ni * 8 + 2 * t;
            *(float2*)(Y + ((size_t)r0 * SEQ + n) * HDIM + c0) =
                make_float2(acc[mi][ni][0], acc[mi][ni][1]);
            *(float2*)(Y + ((size_t)(r0 + 8) * SEQ + n) * HDIM + c0) =
                make_float2(acc[mi][ni][2], acc[mi][ni][3]);
        }
    }
}

// ---------------------------------------------------------------------------
// Kernel B: attention per (b, h) — SIMT (small GEMMs + softmax/top-5)
// ---------------------------------------------------------------------------
__global__ __launch_bounds__(256) void attn_kernel(float* __restrict__ d_out, int write_attn)
{
    __shared__ float qs[SEQ * 64];
    __shared__ float ks[SEQ * 64];
    __shared__ float sc[SEQ * 64];

    const int bh = blockIdx.x;
    const int b  = bh >> 3;
    const int h  = bh & 7;

    const int tid  = threadIdx.x;
    const int lane = tid & 31;
    const int warp = tid >> 5;
    const int tx   = tid & 15;
    const int ty   = tid >> 4;

    const float* qb = g_qh + (size_t)b * SEQ * HDIM + (size_t)h * DK;
    const float* kb = g_kh + (size_t)b * SEQ * HDIM + (size_t)h * DK;
    const float* vb = g_vh + (size_t)b * SEQ * HDIM + (size_t)h * DK;

    for (int i = tid; i < 1024; i += 256) {
        int r = i >> 4, c = (i & 15) * 4;
        *reinterpret_cast<float4*>(&qs[r * 64 + c]) =
            *reinterpret_cast<const float4*>(qb + (size_t)r * HDIM + c);
    }
    for (int i = tid; i < 1024; i += 256) {
        int r = i & 63, c = (i >> 6) * 4;
        float4 kv = *reinterpret_cast<const float4*>(kb + (size_t)r * HDIM + c);
        ks[(c + 0) * 64 + r] = kv.x;
        ks[(c + 1) * 64 + r] = kv.y;
        ks[(c + 2) * 64 + r] = kv.z;
        ks[(c + 3) * 64 + r] = kv.w;
    }
    __syncthreads();

    {
        float acc[4][4] = {};
        #pragma unroll 4
        for (int d = 0; d < 64; d++) {
            float4 bb = *reinterpret_cast<const float4*>(&ks[d * 64 + tx * 4]);
            #pragma unroll
            for (int ii = 0; ii < 4; ii++) {
                float a = qs[(ty * 4 + ii) * 64 + d];
                acc[ii][0] += a * bb.x;
                acc[ii][1] += a * bb.y;
                acc[ii][2] += a * bb.z;
                acc[ii][3] += a * bb.w;
            }
        }
        #pragma unroll
        for (int ii = 0; ii < 4; ii++)
            #pragma unroll
            for (int jj = 0; jj < 4; jj++)
                sc[(ty * 4 + ii) * 64 + tx * 4 + jj] = acc[ii][jj] * 0.125f;
    }
    __syncthreads();

    for (int i = tid; i < 1024; i += 256) {
        int r = i >> 4, c = (i & 15) * 4;
        *reinterpret_cast<float4*>(&qs[r * 64 + c]) =
            *reinterpret_cast<const float4*>(vb + (size_t)r * HDIM + c);
    }

    const unsigned FULL = 0xffffffffu;
    for (int rr = 0; rr < 8; rr++) {
        int r = warp * 8 + rr;
        float s0 = sc[r * 64 + lane];
        float s1 = sc[r * 64 + 32 + lane];

        float m = fmaxf(s0, s1);
        #pragma unroll
        for (int off = 16; off; off >>= 1) m = fmaxf(m, __shfl_xor_sync(FULL, m, off));
        float e0 = expf(s0 - m), e1 = expf(s1 - m);
        float s = e0 + e1;
        #pragma unroll
        for (int off = 16; off; off >>= 1) s += __shfl_xor_sync(FULL, s, off);
        float p0 = e0 / s, p1 = e1 / s;

        float a = p0, c = p1, kth = 0.0f;
        #pragma unroll
        for (int tI = 0; tI < 5; tI++) {
            float mm = fmaxf(a, c);
            #pragma unroll
            for (int off = 16; off; off >>= 1) mm = fmaxf(mm, __shfl_xor_sync(FULL, mm, off));
            kth = mm;
            unsigned ba = __ballot_sync(FULL, a == mm);
            unsigned bc = __ballot_sync(FULL, c == mm);
            if (ba) { if (lane == __ffs(ba) - 1) a = -1e30f; }
            else    { if (lane == __ffs(bc) - 1) c = -1e30f; }
        }

        float delta = kth + EPS_F;
        float w0 = fmaxf(p0 - delta, 0.0f);
        float w1 = fmaxf(p1 - delta, 0.0f);
        float ws = w0 + w1;
        #pragma unroll
        for (int off = 16; off; off >>= 1) ws += __shfl_xor_sync(FULL, ws, off);
        float denom = ws + EPS_F;
        w0 /= denom;
        w1 /= denom;

        sc[r * 64 + lane]      = w0;
        sc[r * 64 + 32 + lane] = w1;
        if (write_attn) {
            size_t ab = (size_t)ATTN_OFF + (((size_t)(h * BATCH + b) * 64 + r) * 64);
            d_out[ab + lane]      = w0;
            d_out[ab + 32 + lane] = w1;
        }
    }
    __syncthreads();

    {
        float acc[4][4] = {};
        #pragma unroll 4
        for (int j = 0; j < 64; j++) {
            float4 bb = *reinterpret_cast<const float4*>(&qs[j * 64 + tx * 4]);
            #pragma unroll
            for (int ii = 0; ii < 4; ii++) {
                float p = sc[(ty * 4 + ii) * 64 + j];
                acc[ii][0] += p * bb.x;
                acc[ii][1] += p * bb.y;
                acc[ii][2] += p * bb.z;
                acc[ii][3] += p * bb.w;
            }
        }
        #pragma unroll
        for (int ii = 0; ii < 4; ii++) {
            int qq = ty * 4 + ii;
            float4 r = make_float4(acc[ii][0], acc[ii][1], acc[ii][2], acc[ii][3]);
            *reinterpret_cast<float4*>(g_o + ((size_t)b * SEQ + qq) * HDIM + (size_t)h * DK + tx * 4) = r;
        }
    }
}

// ---------------------------------------------------------------------------
// Kernel C: fc + gate via split-bf16 mma.sync, fused gated-tanh epilogue.
//   (16384 x 512) @ (512 x 512)^T twice, shared A. CTA tile M=128, N=64, BK=16.
//   8 warps as 2x4; warp tile 64x16 per matrix.
// grid = (128, 8), block = 256
// ---------------------------------------------------------------------------
__global__ __launch_bounds__(256, 2) void out_mma(
    const float* __restrict__ fc_w, const float* __restrict__ fc_b,
    const float* __restrict__ gw,   const float* __restrict__ gb,
    float* __restrict__ d_out, int write_scalar)
{
    __shared__ __align__(16) uint32_t Ahi[128 * PA], Alo[128 * PA];   // A[m][kpair]
    __shared__ __align__(16) uint32_t Bfh[64 * PA],  Bfl[64 * PA];    // fc_w[o][kpair]
    __shared__ __align__(16) uint32_t Bgh[64 * PA],  Bgl[64 * PA];    // gate_w[o][kpair]
    __shared__ float sbf[64], sbg[64];

    const int m0 = blockIdx.x * 128;
    const int o0 = blockIdx.y * 64;

    const int tid  = threadIdx.x;
    const int wid  = tid >> 5;
    const int lane = tid & 31;
    const int g    = lane >> 2;
    const int t    = lane & 3;
    const int warp_m = (wid & 1) * 64;
    const int warp_n = (wid >> 1) * 16;

    const int ar = tid >> 1, sA = tid & 1;          // A loader
    const int bsel = tid >> 7;                      // 0 -> fc, 1 -> gate
    const int bidx = tid & 127;
    const int br = bidx >> 1, sB = bidx & 1;        // B loader: o-row, k-half

    if (tid < 64) { sbf[tid] = fc_b[o0 + tid]; sbg[tid] = gb[o0 + tid]; }

    float accf[4][2][4] = {};
    float accg[4][2][4] = {};

    for (int it = 0; it < 32; ++it) {
        const int k0 = it * 16;

        {
            const float* ap = g_o + (size_t)(m0 + ar) * HDIM + k0 + sA * 8;
            float4 f0 = *(const float4*)ap;
            float4 f1 = *(const float4*)(ap + 4);
            uint4 H, L;
            bsplit2(f0.x, f0.y, H.x, L.x);
            bsplit2(f0.z, f0.w, H.y, L.y);
            bsplit2(f1.x, f1.y, H.z, L.z);
            bsplit2(f1.z, f1.w, H.w, L.w);
            *(uint4*)&Ahi[ar * PA + sA * 4] = H;
            *(uint4*)&Alo[ar * PA + sA * 4] = L;
        }
        {
            const float* src = (bsel ? gw : fc_w) + (size_t)(o0 + br) * HDIM + k0 + sB * 8;
            float4 f0 = *(const float4*)src;
            float4 f1 = *(const float4*)(src + 4);
            uint4 H, L;
            bsplit2(f0.x, f0.y, H.x, L.x);
            bsplit2(f0.z, f0.w, H.y, L.y);
            bsplit2(f1.x, f1.y, H.z, L.z);
            bsplit2(f1.z, f1.w, H.w, L.w);
            if (bsel) {
                *(uint4*)&Bgh[br * PA + sB * 4] = H;
                *(uint4*)&Bgl[br * PA + sB * 4] = L;
            } else {
                *(uint4*)&Bfh[br * PA + sB * 4] = H;
                *(uint4*)&Bfl[br * PA + sB * 4] = L;
            }
        }
        __syncthreads();

        uint32_t af[4][4], bfh[2][2], bgh[2][2], bq[2][2], bp[2][2];
        #pragma unroll
        for (int mi = 0; mi < 4; ++mi) {
            const int rb = warp_m + mi * 16;
            af[mi][0] = Ahi[(rb + g)     * PA + t];
            af[mi][1] = Ahi[(rb + g + 8) * PA + t];
            af[mi][2] = Ahi[(rb + g)     * PA + t + 4];
            af[mi][3] = Ahi[(rb + g + 8) * PA + t + 4];
        }
        #pragma unroll
        for (int ni = 0; ni < 2; ++ni) {
            const int nb = warp_n + ni * 8;
            bfh[ni][0] = Bfh[(nb + g) * PA + t];
            bfh[ni][1] = Bfh[(nb + g) * PA + t + 4];
            bgh[ni][0] = Bgh[(nb + g) * PA + t];
            bgh[ni][1] = Bgh[(nb + g) * PA + t + 4];
        }
        #pragma unroll
        for (int mi = 0; mi < 4; ++mi)
            #pragma unroll
            for (int ni = 0; ni < 2; ++ni) {
                mma_bf16(accf[mi][ni], af[mi], bfh[ni]);   // hi*hi
                mma_bf16(accg[mi][ni], af[mi], bgh[ni]);
            }

        #pragma unroll
        for (int ni = 0; ni < 2; ++ni) {
            const int nb = warp_n + ni * 8;
            bq[ni][0] = Bfl[(nb + g) * PA + t];
            bq[ni][1] = Bfl[(nb + g) * PA + t + 4];
            bp[ni][0] = Bgl[(nb + g) * PA + t];
            bp[ni][1] = Bgl[(nb + g) * PA + t + 4];
        }
        #pragma unroll
        for (int mi = 0; mi < 4; ++mi)
            #pragma unroll
            for (int ni = 0; ni < 2; ++ni) {
                mma_bf16(accf[mi][ni], af[mi], bq[ni]);    // hi*lo
                mma_bf16(accg[mi][ni], af[mi], bp[ni]);
            }

        #pragma unroll
        for (int mi = 0; mi < 4; ++mi) {
            const int rb = warp_m + mi * 16;
            af[mi][0] = Alo[(rb + g)     * PA + t];
            af[mi][1] = Alo[(rb + g + 8) * PA + t];
            af[mi][2] = Alo[(rb + g)     * PA + t + 4];
            af[mi][3] = Alo[(rb + g + 8) * PA + t + 4];
        }
        #pragma unroll
        for (int mi = 0; mi < 4; ++mi)
            #pragma unroll
            for (int ni = 0; ni < 2; ++ni) {
                mma_bf16(accf[mi][ni], af[mi], bfh[ni]);   // lo*hi
                mma_bf16(accg[mi][ni], af[mi], bgh[ni]);
            }

        __syncthreads();
    }

    #pragma unroll
    for (int mi = 0; mi < 4; ++mi) {
        const int r0 = m0 + warp_m + mi * 16 + g;
        #pragma unroll
        for (int ni = 0; ni < 2; ++ni) {
            const int lc = warp_n + ni * 8 + 2 * t;
            const int c0 = o0 + lc;
            #pragma unroll
            for (int half = 0; half < 2; ++half) {
                const int row = r0 + half * 8;
                float f0 = accf[mi][ni][half * 2 + 0] + sbf[lc];
                float f1 = accf[mi][ni][half * 2 + 1] + sbf[lc + 1];
                float g0 = accg[mi][ni][half * 2 + 0] + sbg[lc];
                float g1 = accg[mi][ni][half * 2 + 1] + sbg[lc + 1];
                float s0 = 1.0f / (1.0f + expf(-g0));
                float s1 = 1.0f / (1.0f + expf(-g1));
                *(float2*)(d_out + (size_t)row * DMODEL + c0) =
                    make_float2(s0 * tanhf(f0), s1 * tanhf(f1));
            }
        }
    }

    if (write_scalar && blockIdx.x == 0 && blockIdx.y == 0 && tid == 0)
        d_out[SCALAR_OFF] = 0.0f;
}

// ---------------------------------------------------------------------------
extern "C" void kernel_launch(void* const* d_in, const int* in_sizes, int n_in,
                              void* d_out, int out_size)
{
    const float* q      = (const float*)d_in[0];
    const float* k      = (const float*)d_in[1];
    const float* v      = (const float*)d_in[2];
    const float* Wq     = (const float*)d_in[3];
    const float* Wk     = (const float*)d_in[4];
    const float* Wv     = (const float*)d_in[5];
    const float* fc_w   = (const float*)d_in[6];
    const float* fc_b   = (const float*)d_in[7];
    const float* gate_w = (const float*)d_in[8];
    const float* gate_b = (const float*)d_in[9];
    float* out = (float*)d_out;

    const int write_attn   = (out_size >= ATTN_OFF + ATTN_ELEMS) ? 1 : 0;
    const int write_scalar = (out_size >= SCALAR_OFF + 1) ? 1 : 0;

    dim3 gA(2, 4, 192);
    proj_mma<<<gA, 256>>>(q, k, v, Wq, Wk, Wv);

    attn_kernel<<<2048, 256>>>(out, write_attn);

    dim3 gC(128, 8);
    out_mma<<<gC, 256>>>(fc_w, fc_b, gate_w, gate_b, out, write_scalar);
}